// round 1
// baseline (speedup 1.0000x reference)
#include <cuda_runtime.h>
#include <cstdint>

// Problem constants
#define NTOK   32768          // 8 * 4096 tokens
#define DF     32             // fiber dim
#define STRIDE 36             // shared row stride (floats): 16B-aligned, conflict-free columns
#define NS_ITERS 4            // Newton-Schulz iterations (delta0<=0.16 -> err ~1e-8)
#define PWARPS 4              // warps (tokens) per polar block

// Output layout (float offsets): base | fiber | connection | generators
#define OUT_FIBER 16777216ull   // 32768*512
#define OUT_CONN  50331648ull   // + 32768*1024
#define OUT_GEN   50593792ull   // + 32768*8

// ---------------------------------------------------------------------------
// Kernel 1: pure gathers — base (512 f32/token), connection (8 f32/token),
// plus generators passthrough (8192 f32) in one extra block.
// ---------------------------------------------------------------------------
__global__ void gather_copy_kernel(const int* __restrict__ tokens,
                                   const float* __restrict__ base_w,
                                   const float* __restrict__ conn_w,
                                   const float* __restrict__ gens,
                                   float* __restrict__ out)
{
    int b   = blockIdx.x;
    int tid = threadIdx.x;
    if (b < NTOK) {
        int t = tokens[b];
        // base row: 512 floats = 128 float4, one per thread
        const float4* src = reinterpret_cast<const float4*>(base_w) + (size_t)t * 128;
        float4*       dst = reinterpret_cast<float4*>(out)          + (size_t)b * 128;
        dst[tid] = src[tid];
        // connection row: 8 floats = 2 float4
        if (tid < 2) {
            const float4* cs = reinterpret_cast<const float4*>(conn_w) + (size_t)t * 2;
            float4*       cd = reinterpret_cast<float4*>(out + OUT_CONN) + (size_t)b * 2;
            cd[tid] = cs[tid];
        }
    } else {
        // generators: 8192 floats = 2048 float4
        const float4* gs = reinterpret_cast<const float4*>(gens);
        float4*       gd = reinterpret_cast<float4*>(out + OUT_GEN);
        #pragma unroll
        for (int i = 0; i < 16; i++) gd[tid + 128 * i] = gs[tid + 128 * i];
    }
}

// ---------------------------------------------------------------------------
// Kernel 2: per-token polar factor via Newton-Schulz.
//   X <- X * (1.5 I - 0.5 X^T X)
// One warp per 32x32 matrix. Lane j owns column j of all intermediates.
// Matrix lives in shared (ping-pong buffers); row reads are warp-uniform
// (broadcast, vectorized float4), column reads/writes are conflict-free.
// ---------------------------------------------------------------------------
__global__ void __launch_bounds__(PWARPS * 32)
polar_kernel(const int* __restrict__ tokens,
             const float* __restrict__ fiber_w,
             float* __restrict__ out)
{
    __shared__ float bufA[PWARPS][DF * STRIDE];
    __shared__ float bufB[PWARPS][DF * STRIDE];

    const int warp = threadIdx.x >> 5;
    const int lane = threadIdx.x & 31;
    const int tok  = blockIdx.x * PWARPS + warp;   // grid sized exactly

    float* XA = bufA[warp];
    float* XB = bufB[warp];

    const int t = tokens[tok];
    const float* src = fiber_w + (size_t)t * (DF * DF);

    // Load 32x32 matrix into shared (coalesced gmem, conflict-free smem)
    #pragma unroll 1
    for (int r = 0; r < DF; r++)
        XA[r * STRIDE + lane] = src[r * 32 + lane];
    __syncwarp();

    float* cur = XA;
    float* nxt = XB;

    #pragma unroll 1
    for (int it = 0; it < NS_ITERS - 1; it++) {
        // ---- y = column `lane` of X^T X -------------------------------
        float y[DF];
        #pragma unroll
        for (int i = 0; i < DF; i++) y[i] = 0.0f;

        #pragma unroll 1
        for (int k = 0; k < DF; k++) {
            float xk = cur[k * STRIDE + lane];                         // my column elem
            const float4* row = reinterpret_cast<const float4*>(cur + k * STRIDE);
            #pragma unroll
            for (int q = 0; q < 8; q++) {                              // broadcast row
                float4 v = row[q];
                y[q * 4 + 0] = fmaf(v.x, xk, y[q * 4 + 0]);
                y[q * 4 + 1] = fmaf(v.y, xk, y[q * 4 + 1]);
                y[q * 4 + 2] = fmaf(v.z, xk, y[q * 4 + 2]);
                y[q * 4 + 3] = fmaf(v.w, xk, y[q * 4 + 3]);
            }
        }
        // ---- t = 1.5 e_lane - 0.5 y (in place) ------------------------
        #pragma unroll
        for (int k = 0; k < DF; k++)
            y[k] = ((k == lane) ? 1.5f : 0.0f) - 0.5f * y[k];

        // ---- column `lane` of Z = X * t, write to other buffer --------
        #pragma unroll 1
        for (int i = 0; i < DF; i++) {
            const float4* row = reinterpret_cast<const float4*>(cur + i * STRIDE);
            float acc = 0.0f;
            #pragma unroll
            for (int q = 0; q < 8; q++) {
                float4 v = row[q];
                acc = fmaf(v.x, y[q * 4 + 0], acc);
                acc = fmaf(v.y, y[q * 4 + 1], acc);
                acc = fmaf(v.z, y[q * 4 + 2], acc);
                acc = fmaf(v.w, y[q * 4 + 3], acc);
            }
            nxt[i * STRIDE + lane] = acc;
        }
        __syncwarp();
        float* tmp = cur; cur = nxt; nxt = tmp;
    }

    // ---- final iteration: identical math, streams result to GMEM ------
    {
        float y[DF];
        #pragma unroll
        for (int i = 0; i < DF; i++) y[i] = 0.0f;

        #pragma unroll 1
        for (int k = 0; k < DF; k++) {
            float xk = cur[k * STRIDE + lane];
            const float4* row = reinterpret_cast<const float4*>(cur + k * STRIDE);
            #pragma unroll
            for (int q = 0; q < 8; q++) {
                float4 v = row[q];
                y[q * 4 + 0] = fmaf(v.x, xk, y[q * 4 + 0]);
                y[q * 4 + 1] = fmaf(v.y, xk, y[q * 4 + 1]);
                y[q * 4 + 2] = fmaf(v.z, xk, y[q * 4 + 2]);
                y[q * 4 + 3] = fmaf(v.w, xk, y[q * 4 + 3]);
            }
        }
        #pragma unroll
        for (int k = 0; k < DF; k++)
            y[k] = ((k == lane) ? 1.5f : 0.0f) - 0.5f * y[k];

        float* dst = out + OUT_FIBER + (size_t)tok * (DF * DF);
        #pragma unroll 1
        for (int i = 0; i < DF; i++) {
            const float4* row = reinterpret_cast<const float4*>(cur + i * STRIDE);
            float acc = 0.0f;
            #pragma unroll
            for (int q = 0; q < 8; q++) {
                float4 v = row[q];
                acc = fmaf(v.x, y[q * 4 + 0], acc);
                acc = fmaf(v.y, y[q * 4 + 1], acc);
                acc = fmaf(v.z, y[q * 4 + 2], acc);
                acc = fmaf(v.w, y[q * 4 + 3], acc);
            }
            dst[i * 32 + lane] = acc;       // coalesced
        }
    }
}

// ---------------------------------------------------------------------------
extern "C" void kernel_launch(void* const* d_in, const int* in_sizes, int n_in,
                              void* d_out, int out_size)
{
    const int*   tokens  = (const int*)  d_in[0];
    const float* base_w  = (const float*)d_in[1];
    const float* fiber_w = (const float*)d_in[2];
    const float* conn_w  = (const float*)d_in[3];
    const float* gens    = (const float*)d_in[4];
    float* out = (float*)d_out;

    gather_copy_kernel<<<NTOK + 1, 128>>>(tokens, base_w, conn_w, gens, out);
    polar_kernel<<<NTOK / PWARPS, PWARPS * 32>>>(tokens, fiber_w, out);
}

// round 2
// speedup vs baseline: 1.7653x; 1.7653x over previous
#include <cuda_runtime.h>
#include <cstdint>

// Problem constants
#define NTOK   32768          // 8 * 4096 tokens
#define DF     32             // fiber dim
#define NS_ITERS 3            // worst-case sigma err ~1.2e-5 << 1e-3 gate
#define PWARPS 2              // warps per polar block (each warp = 2 tokens)

// Output layout (float offsets): base | fiber | connection | generators
#define OUT_FIBER 16777216ull   // 32768*512
#define OUT_CONN  50331648ull   // + 32768*1024
#define OUT_GEN   50593792ull   // + 32768*8

// ---------------------------------------------------------------------------
// f32x2 packed-math helpers (FFMA2 is real HW on sm_103a, PTX-only)
// ---------------------------------------------------------------------------
__device__ __forceinline__ void ffma2(unsigned long long& d,
                                      unsigned long long a,
                                      unsigned long long b) {
    asm("fma.rn.f32x2 %0, %1, %2, %0;" : "+l"(d) : "l"(a), "l"(b));
}
__device__ __forceinline__ unsigned long long fadd2(unsigned long long a,
                                                    unsigned long long b) {
    unsigned long long r;
    asm("add.rn.f32x2 %0, %1, %2;" : "=l"(r) : "l"(a), "l"(b));
    return r;
}
__device__ __forceinline__ unsigned long long pack2(float lo, float hi) {
    unsigned long long r;
    asm("mov.b64 %0, {%1, %2};" : "=l"(r) : "f"(lo), "f"(hi));
    return r;
}
__device__ __forceinline__ float2 unpack2(unsigned long long v) {
    float2 f;
    asm("mov.b64 {%0, %1}, %2;" : "=f"(f.x), "=f"(f.y) : "l"(v));
    return f;
}

// ---------------------------------------------------------------------------
// Kernel 1: pure gathers — base (512 f32/token), connection (8 f32/token),
// plus generators passthrough (8192 f32) in one extra block.
// ---------------------------------------------------------------------------
__global__ void gather_copy_kernel(const int* __restrict__ tokens,
                                   const float* __restrict__ base_w,
                                   const float* __restrict__ conn_w,
                                   const float* __restrict__ gens,
                                   float* __restrict__ out)
{
    int b   = blockIdx.x;
    int tid = threadIdx.x;
    if (b < NTOK) {
        int t = tokens[b];
        const float4* src = reinterpret_cast<const float4*>(base_w) + (size_t)t * 128;
        float4*       dst = reinterpret_cast<float4*>(out)          + (size_t)b * 128;
        dst[tid] = src[tid];
        if (tid < 2) {
            const float4* cs = reinterpret_cast<const float4*>(conn_w) + (size_t)t * 2;
            float4*       cd = reinterpret_cast<float4*>(out + OUT_CONN) + (size_t)b * 2;
            cd[tid] = cs[tid];
        }
    } else {
        const float4* gs = reinterpret_cast<const float4*>(gens);
        float4*       gd = reinterpret_cast<float4*>(out + OUT_GEN);
        #pragma unroll
        for (int i = 0; i < 16; i++) gd[tid + 128 * i] = gs[tid + 128 * i];
    }
}

// ---------------------------------------------------------------------------
// Kernel 2: polar factor via Newton-Schulz, TWO tokens per warp via f32x2.
// Shared element S[k][j] = (X_t0[k][j], X_t1[k][j]) as an 8-byte pair.
// Lane j owns column j of both tokens. Row broadcasts feed both tokens per
// LDS.128; every FFMA2 does 2 MACs/lane. Ping-pong buffers per warp.
// ---------------------------------------------------------------------------
__global__ void __launch_bounds__(PWARPS * 32)
polar_kernel(const int* __restrict__ tokens,
             const float* __restrict__ fiber_w,
             float* __restrict__ out)
{
    // 32 rows x 32 pair-columns x 8B = 8KB per warp per buffer
    __shared__ unsigned long long sA[PWARPS][DF * DF];
    __shared__ unsigned long long sB[PWARPS][DF * DF];

    const int warp = threadIdx.x >> 5;
    const int lane = threadIdx.x & 31;
    const int pair = blockIdx.x * PWARPS + warp;    // warp-pair index
    const int tok0 = pair * 2;
    const int tok1 = tok0 + 1;

    unsigned long long* XA = sA[warp];
    unsigned long long* XB = sB[warp];

    const int t0 = tokens[tok0];
    const int t1 = tokens[tok1];
    const float* s0 = fiber_w + (size_t)t0 * (DF * DF);
    const float* s1 = fiber_w + (size_t)t1 * (DF * DF);

    // Load both 32x32 matrices, interleaved as pairs (coalesced LDG)
    #pragma unroll 1
    for (int r = 0; r < DF; r++)
        XA[r * DF + lane] = pack2(s0[r * DF + lane], s1[r * DF + lane]);
    __syncwarp();

    unsigned long long* cur = XA;
    unsigned long long* nxt = XB;

    #pragma unroll 1
    for (int it = 0; it < NS_ITERS; it++) {
        // ---- y = column `lane` of X^T X (both tokens packed) -----------
        unsigned long long y[DF];
        #pragma unroll
        for (int i = 0; i < DF; i++) y[i] = 0ull;

        #pragma unroll 2
        for (int k = 0; k < DF; k++) {
            unsigned long long xk = cur[k * DF + lane];           // own col elem pair
            const ulonglong2* row = reinterpret_cast<const ulonglong2*>(cur + k * DF);
            #pragma unroll
            for (int q = 0; q < 16; q++) {                        // broadcast row (LDS.128)
                ulonglong2 v = row[q];
                ffma2(y[2 * q + 0], v.x, xk);
                ffma2(y[2 * q + 1], v.y, xk);
            }
        }

        // ---- T = 1.5 I - 0.5 Y (in place, per pair) ---------------------
        #pragma unroll
        for (int k = 0; k < DF; k++) {
            float2 f = unpack2(y[k]);
            float  d = (k == lane) ? 1.5f : 0.0f;
            y[k] = pack2(d - 0.5f * f.x, d - 0.5f * f.y);
        }

        const bool last = (it == NS_ITERS - 1);
        float* dst0 = out + OUT_FIBER + (size_t)tok0 * (DF * DF);
        float* dst1 = out + OUT_FIBER + (size_t)tok1 * (DF * DF);

        // ---- column `lane` of Z = X * T --------------------------------
        #pragma unroll 1
        for (int i = 0; i < DF; i++) {
            const ulonglong2* row = reinterpret_cast<const ulonglong2*>(cur + i * DF);
            unsigned long long a0 = 0ull, a1 = 0ull;   // split dep chain
            #pragma unroll
            for (int q = 0; q < 16; q += 2) {
                ulonglong2 v0 = row[q];
                ulonglong2 v1 = row[q + 1];
                ffma2(a0, v0.x, y[2 * q + 0]);
                ffma2(a0, v0.y, y[2 * q + 1]);
                ffma2(a1, v1.x, y[2 * q + 2]);
                ffma2(a1, v1.y, y[2 * q + 3]);
            }
            unsigned long long acc = fadd2(a0, a1);
            if (last) {
                float2 z = unpack2(acc);
                dst0[i * DF + lane] = z.x;             // coalesced STG
                dst1[i * DF + lane] = z.y;
            } else {
                nxt[i * DF + lane] = acc;
            }
        }
        __syncwarp();
        unsigned long long* tmp = cur; cur = nxt; nxt = tmp;
    }
}

// ---------------------------------------------------------------------------
extern "C" void kernel_launch(void* const* d_in, const int* in_sizes, int n_in,
                              void* d_out, int out_size)
{
    const int*   tokens  = (const int*)  d_in[0];
    const float* base_w  = (const float*)d_in[1];
    const float* fiber_w = (const float*)d_in[2];
    const float* conn_w  = (const float*)d_in[3];
    const float* gens    = (const float*)d_in[4];
    float* out = (float*)d_out;

    gather_copy_kernel<<<NTOK + 1, 128>>>(tokens, base_w, conn_w, gens, out);
    polar_kernel<<<NTOK / 2 / PWARPS, PWARPS * 32>>>(tokens, fiber_w, out);
}

// round 3
// speedup vs baseline: 2.1184x; 1.2000x over previous
#include <cuda_runtime.h>
#include <cstdint>

#define NTOK   32768
#define DF     32
#define NS_ITERS 3
#define PWARPS 2              // warps per polar block; each warp = 4 tokens

// Output layout (float offsets): base | fiber | connection | generators
#define OUT_FIBER 16777216ull
#define OUT_CONN  50331648ull
#define OUT_GEN   50593792ull

typedef unsigned long long u64;

// ---------------------------------------------------------------------------
// f32x2 packed-math helpers
// ---------------------------------------------------------------------------
__device__ __forceinline__ void ffma2(u64& d, u64 a, u64 b) {
    asm("fma.rn.f32x2 %0, %1, %2, %0;" : "+l"(d) : "l"(a), "l"(b));
}
__device__ __forceinline__ u64 ffma2r(u64 a, u64 b, u64 c) {
    u64 r;
    asm("fma.rn.f32x2 %0, %1, %2, %3;" : "=l"(r) : "l"(a), "l"(b), "l"(c));
    return r;
}
__device__ __forceinline__ u64 fadd2(u64 a, u64 b) {
    u64 r;
    asm("add.rn.f32x2 %0, %1, %2;" : "=l"(r) : "l"(a), "l"(b));
    return r;
}
__device__ __forceinline__ u64 pack2(float lo, float hi) {
    u64 r;
    asm("mov.b64 %0, {%1, %2};" : "=l"(r) : "f"(lo), "f"(hi));
    return r;
}
__device__ __forceinline__ float2 unpack2(u64 v) {
    float2 f;
    asm("mov.b64 {%0, %1}, %2;" : "=f"(f.x), "=f"(f.y) : "l"(v));
    return f;
}

// ---------------------------------------------------------------------------
// Kernel 1: gathers (base, connection) + generators passthrough
// ---------------------------------------------------------------------------
__global__ void gather_copy_kernel(const int* __restrict__ tokens,
                                   const float* __restrict__ base_w,
                                   const float* __restrict__ conn_w,
                                   const float* __restrict__ gens,
                                   float* __restrict__ out)
{
    int b   = blockIdx.x;
    int tid = threadIdx.x;
    if (b < NTOK) {
        int t = tokens[b];
        const float4* src = reinterpret_cast<const float4*>(base_w) + (size_t)t * 128;
        float4*       dst = reinterpret_cast<float4*>(out)          + (size_t)b * 128;
        dst[tid] = src[tid];
        if (tid < 2) {
            const float4* cs = reinterpret_cast<const float4*>(conn_w) + (size_t)t * 2;
            float4*       cd = reinterpret_cast<float4*>(out + OUT_CONN) + (size_t)b * 2;
            cd[tid] = cs[tid];
        }
    } else {
        const float4* gs = reinterpret_cast<const float4*>(gens);
        float4*       gd = reinterpret_cast<float4*>(out + OUT_GEN);
        #pragma unroll
        for (int i = 0; i < 16; i++) gd[tid + 128 * i] = gs[tid + 128 * i];
    }
}

// ---------------------------------------------------------------------------
// One Newton-Schulz iteration: X <- X (1.5I - 0.5 X^T X), in-place in smem.
// Lane owns columns (2c, 2c+1) of its half's token pair (f32x2 packed).
// ---------------------------------------------------------------------------
template<bool LAST>
__device__ __forceinline__ void ns_iter(u64* __restrict__ B, int c,
                                        float* __restrict__ d0,
                                        float* __restrict__ d1)
{
    u64 y0[DF], y1[DF];
    #pragma unroll
    for (int i = 0; i < DF; i++) { y0[i] = 0ull; y1[i] = 0ull; }

    // ---- Y = X^T X: columns 2c, 2c+1 ----------------------------------
    #pragma unroll 1
    for (int k = 0; k < DF; k++) {
        const ulonglong2* row = reinterpret_cast<const ulonglong2*>(B + k * DF);
        ulonglong2 xk = *reinterpret_cast<const ulonglong2*>(B + k * DF + 2 * c);
        #pragma unroll
        for (int q = 0; q < 16; q++) {
            ulonglong2 v = row[q];
            ffma2(y0[2 * q + 0], v.x, xk.x);
            ffma2(y0[2 * q + 1], v.y, xk.x);
            ffma2(y1[2 * q + 0], v.x, xk.y);
            ffma2(y1[2 * q + 1], v.y, xk.y);
        }
    }

    // ---- T = 1.5 I - 0.5 Y --------------------------------------------
    const u64 NH  = pack2(-0.5f, -0.5f);
    const u64 THR = pack2(1.5f, 1.5f);
    #pragma unroll
    for (int k = 0; k < DF; k++) {
        y0[k] = ffma2r(y0[k], NH, (k == 2 * c)     ? THR : 0ull);
        y1[k] = ffma2r(y1[k], NH, (k == 2 * c + 1) ? THR : 0ull);
    }

    // ---- Z = X * T (row i consumed before row i written: in-place) ----
    #pragma unroll 1
    for (int i = 0; i < DF; i++) {
        const ulonglong2* row = reinterpret_cast<const ulonglong2*>(B + i * DF);
        u64 a0 = 0ull, b0 = 0ull, a1 = 0ull, b1 = 0ull;
        #pragma unroll
        for (int q = 0; q < 16; q += 2) {
            ulonglong2 v = row[q];
            ulonglong2 w = row[q + 1];
            ffma2(a0, v.x, y0[2 * q + 0]); ffma2(a0, v.y, y0[2 * q + 1]);
            ffma2(b0, w.x, y0[2 * q + 2]); ffma2(b0, w.y, y0[2 * q + 3]);
            ffma2(a1, v.x, y1[2 * q + 0]); ffma2(a1, v.y, y1[2 * q + 1]);
            ffma2(b1, w.x, y1[2 * q + 2]); ffma2(b1, w.y, y1[2 * q + 3]);
        }
        u64 z0 = fadd2(a0, b0);
        u64 z1 = fadd2(a1, b1);
        if (LAST) {
            float2 f0 = unpack2(z0);          // (tokEven, tokOdd) col 2c
            float2 f1 = unpack2(z1);          // (tokEven, tokOdd) col 2c+1
            float2 pe = make_float2(f0.x, f1.x);
            float2 po = make_float2(f0.y, f1.y);
            *reinterpret_cast<float2*>(d0 + i * DF + 2 * c) = pe;
            *reinterpret_cast<float2*>(d1 + i * DF + 2 * c) = po;
        } else {
            ulonglong2 z; z.x = z0; z.y = z1;
            *reinterpret_cast<ulonglong2*>(B + i * DF + 2 * c) = z;
        }
    }
    __syncwarp();
}

// ---------------------------------------------------------------------------
// Kernel 2: polar factor. Warp = 4 tokens (2 f32x2 pairs, one per half-warp).
// ---------------------------------------------------------------------------
__global__ void __launch_bounds__(PWARPS * 32)
polar_kernel(const int* __restrict__ tokens,
             const float* __restrict__ fiber_w,
             float* __restrict__ out)
{
    __shared__ u64 sm[PWARPS][2][DF * DF];   // 16KB per warp

    const int warp = threadIdx.x >> 5;
    const int lane = threadIdx.x & 31;
    const int h    = lane >> 4;              // which token pair this half owns
    const int c    = lane & 15;              // owns columns 2c, 2c+1
    const int tokb = (blockIdx.x * PWARPS + warp) * 4;

    u64* B = sm[warp][h];

    const int tE = tokens[tokb + 2 * h + 0];
    const int tO = tokens[tokb + 2 * h + 1];
    const float* sE = fiber_w + (size_t)tE * (DF * DF);
    const float* sO = fiber_w + (size_t)tO * (DF * DF);

    // Load: half h fills its pair's matrix; lane covers columns 2c, 2c+1
    #pragma unroll 1
    for (int r = 0; r < DF; r++) {
        float2 vE = *reinterpret_cast<const float2*>(sE + r * DF + 2 * c);
        float2 vO = *reinterpret_cast<const float2*>(sO + r * DF + 2 * c);
        ulonglong2 p;
        p.x = pack2(vE.x, vO.x);
        p.y = pack2(vE.y, vO.y);
        *reinterpret_cast<ulonglong2*>(B + r * DF + 2 * c) = p;
    }
    __syncwarp();

    float* d0 = out + OUT_FIBER + (size_t)(tokb + 2 * h) * (DF * DF);
    float* d1 = d0 + DF * DF;

    #pragma unroll 1
    for (int it = 0; it < NS_ITERS - 1; it++)
        ns_iter<false>(B, c, d0, d1);
    ns_iter<true>(B, c, d0, d1);
}

// ---------------------------------------------------------------------------
extern "C" void kernel_launch(void* const* d_in, const int* in_sizes, int n_in,
                              void* d_out, int out_size)
{
    const int*   tokens  = (const int*)  d_in[0];
    const float* base_w  = (const float*)d_in[1];
    const float* fiber_w = (const float*)d_in[2];
    const float* conn_w  = (const float*)d_in[3];
    const float* gens    = (const float*)d_in[4];
    float* out = (float*)d_out;

    gather_copy_kernel<<<NTOK + 1, 128>>>(tokens, base_w, conn_w, gens, out);
    polar_kernel<<<NTOK / 4 / PWARPS, PWARPS * 32>>>(tokens, fiber_w, out);
}

// round 5
// speedup vs baseline: 2.4833x; 1.1723x over previous
#include <cuda_runtime.h>
#include <cstdint>

#define NTOK   32768
#define DF     32
#define NS_ITERS 2            // aggregate rel_err ~1.3e-4 (measured model, 8x margin)
#define PWARPS 2              // warps per polar block; each warp = 4 tokens

// Output layout (float offsets): base | fiber | connection | generators
#define OUT_FIBER 16777216ull
#define OUT_CONN  50331648ull
#define OUT_GEN   50593792ull

typedef unsigned long long u64;

// ---------------------------------------------------------------------------
// f32x2 packed-math helpers (defined BEFORE all uses)
// ---------------------------------------------------------------------------
__device__ __forceinline__ void ffma2(u64& d, u64 a, u64 b) {
    asm("fma.rn.f32x2 %0, %1, %2, %0;" : "+l"(d) : "l"(a), "l"(b));
}
__device__ __forceinline__ u64 ffma2r(u64 a, u64 b, u64 c) {
    u64 r;
    asm("fma.rn.f32x2 %0, %1, %2, %3;" : "=l"(r) : "l"(a), "l"(b), "l"(c));
    return r;
}
__device__ __forceinline__ u64 fadd2(u64 a, u64 b) {
    u64 r;
    asm("add.rn.f32x2 %0, %1, %2;" : "=l"(r) : "l"(a), "l"(b));
    return r;
}
__device__ __forceinline__ u64 pack2(float lo, float hi) {
    u64 r;
    asm("mov.b64 %0, {%1, %2};" : "=l"(r) : "f"(lo), "f"(hi));
    return r;
}
__device__ __forceinline__ float2 unpack2(u64 v) {
    float2 f;
    asm("mov.b64 {%0, %1}, %2;" : "=f"(f.x), "=f"(f.y) : "l"(v));
    return f;
}

// ---------------------------------------------------------------------------
// Kernel 1: gathers (base, connection) + generators passthrough
// ---------------------------------------------------------------------------
__global__ void gather_copy_kernel(const int* __restrict__ tokens,
                                   const float* __restrict__ base_w,
                                   const float* __restrict__ conn_w,
                                   const float* __restrict__ gens,
                                   float* __restrict__ out)
{
    int b   = blockIdx.x;
    int tid = threadIdx.x;
    if (b < NTOK) {
        int t = tokens[b];
        const float4* src = reinterpret_cast<const float4*>(base_w) + (size_t)t * 128;
        float4*       dst = reinterpret_cast<float4*>(out)          + (size_t)b * 128;
        dst[tid] = src[tid];
        if (tid < 2) {
            const float4* cs = reinterpret_cast<const float4*>(conn_w) + (size_t)t * 2;
            float4*       cd = reinterpret_cast<float4*>(out + OUT_CONN) + (size_t)b * 2;
            cd[tid] = cs[tid];
        }
    } else {
        const float4* gs = reinterpret_cast<const float4*>(gens);
        float4*       gd = reinterpret_cast<float4*>(out + OUT_GEN);
        #pragma unroll
        for (int i = 0; i < 16; i++) gd[tid + 128 * i] = gs[tid + 128 * i];
    }
}

// ---------------------------------------------------------------------------
// One Newton-Schulz iteration, fused form:  Z = 1.5*X - 0.5 * X * (X^T X)
// In-place in smem. Lane owns columns (2c, 2c+1) of its half-warp's token
// pair (each element is an f32x2 pack of the two tokens).
// ---------------------------------------------------------------------------
template<bool LAST>
__device__ __forceinline__ void ns_iter(u64* __restrict__ B, int c,
                                        float* __restrict__ d0,
                                        float* __restrict__ d1)
{
    u64 y0[DF], y1[DF];
    #pragma unroll
    for (int i = 0; i < DF; i++) { y0[i] = 0ull; y1[i] = 0ull; }

    // ---- Y = X^T X: columns 2c, 2c+1 ----------------------------------
    #pragma unroll 1
    for (int k = 0; k < DF; k++) {
        const ulonglong2* row = reinterpret_cast<const ulonglong2*>(B + k * DF);
        ulonglong2 xk = *reinterpret_cast<const ulonglong2*>(B + k * DF + 2 * c);
        #pragma unroll
        for (int q = 0; q < 16; q++) {
            ulonglong2 v = row[q];
            ffma2(y0[2 * q + 0], v.x, xk.x);
            ffma2(y0[2 * q + 1], v.y, xk.x);
            ffma2(y1[2 * q + 0], v.x, xk.y);
            ffma2(y1[2 * q + 1], v.y, xk.y);
        }
    }

    const u64 NH = pack2(-0.5f, -0.5f);
    const u64 TH = pack2( 1.5f,  1.5f);

    // ---- Z = 1.5 X - 0.5 X*Y (row i consumed before written: in-place) -
    #pragma unroll 1
    for (int i = 0; i < DF; i++) {
        const ulonglong2* row = reinterpret_cast<const ulonglong2*>(B + i * DF);
        u64 a0 = 0ull, b0 = 0ull, a1 = 0ull, b1 = 0ull;
        u64 own0 = 0ull, own1 = 0ull;                 // X[i][2c], X[i][2c+1]
        #pragma unroll
        for (int q = 0; q < 16; q += 2) {
            ulonglong2 v = row[q];
            ulonglong2 w = row[q + 1];
            if (q == (c & ~1)) { if (c & 1) { own0 = w.x; own1 = w.y; }
                                 else       { own0 = v.x; own1 = v.y; } }
            ffma2(a0, v.x, y0[2 * q + 0]); ffma2(a0, v.y, y0[2 * q + 1]);
            ffma2(b0, w.x, y0[2 * q + 2]); ffma2(b0, w.y, y0[2 * q + 3]);
            ffma2(a1, v.x, y1[2 * q + 0]); ffma2(a1, v.y, y1[2 * q + 1]);
            ffma2(b1, w.x, y1[2 * q + 2]); ffma2(b1, w.y, y1[2 * q + 3]);
        }
        // z = 1.5*own - 0.5*(a+b)
        u64 z0 = ffma2r(own0, TH, ffma2r(fadd2(a0, b0), NH, 0ull));
        u64 z1 = ffma2r(own1, TH, ffma2r(fadd2(a1, b1), NH, 0ull));
        if (LAST) {
            float2 f0 = unpack2(z0);                  // (tokE, tokO) col 2c
            float2 f1 = unpack2(z1);                  // (tokE, tokO) col 2c+1
            *reinterpret_cast<float2*>(d0 + i * DF + 2 * c) = make_float2(f0.x, f1.x);
            *reinterpret_cast<float2*>(d1 + i * DF + 2 * c) = make_float2(f0.y, f1.y);
        } else {
            ulonglong2 z; z.x = z0; z.y = z1;
            *reinterpret_cast<ulonglong2*>(B + i * DF + 2 * c) = z;
        }
    }
    __syncwarp();
}

// ---------------------------------------------------------------------------
// Kernel 2: polar factor. Warp = 4 tokens (2 f32x2 pairs, one per half-warp).
// launch_bounds(64,6): cap regs ~168 -> 6 blocks = 12 warps/SM.
// ---------------------------------------------------------------------------
__global__ void __launch_bounds__(PWARPS * 32, 6)
polar_kernel(const int* __restrict__ tokens,
             const float* __restrict__ fiber_w,
             float* __restrict__ out)
{
    __shared__ u64 sm[PWARPS][2][DF * DF];   // 16KB per warp

    const int warp = threadIdx.x >> 5;
    const int lane = threadIdx.x & 31;
    const int h    = lane >> 4;
    const int c    = lane & 15;
    const int tokb = (blockIdx.x * PWARPS + warp) * 4;

    u64* B = sm[warp][h];

    const int tE = tokens[tokb + 2 * h + 0];
    const int tO = tokens[tokb + 2 * h + 1];
    const float* sE = fiber_w + (size_t)tE * (DF * DF);
    const float* sO = fiber_w + (size_t)tO * (DF * DF);

    #pragma unroll 1
    for (int r = 0; r < DF; r++) {
        float2 vE = *reinterpret_cast<const float2*>(sE + r * DF + 2 * c);
        float2 vO = *reinterpret_cast<const float2*>(sO + r * DF + 2 * c);
        ulonglong2 p;
        p.x = pack2(vE.x, vO.x);
        p.y = pack2(vE.y, vO.y);
        *reinterpret_cast<ulonglong2*>(B + r * DF + 2 * c) = p;
    }
    __syncwarp();

    float* d0 = out + OUT_FIBER + (size_t)(tokb + 2 * h) * (DF * DF);
    float* d1 = d0 + DF * DF;

    #pragma unroll 1
    for (int it = 0; it < NS_ITERS - 1; it++)
        ns_iter<false>(B, c, d0, d1);
    ns_iter<true>(B, c, d0, d1);
}

// ---------------------------------------------------------------------------
extern "C" void kernel_launch(void* const* d_in, const int* in_sizes, int n_in,
                              void* d_out, int out_size)
{
    const int*   tokens  = (const int*)  d_in[0];
    const float* base_w  = (const float*)d_in[1];
    const float* fiber_w = (const float*)d_in[2];
    const float* conn_w  = (const float*)d_in[3];
    const float* gens    = (const float*)d_in[4];
    float* out = (float*)d_out;

    gather_copy_kernel<<<NTOK + 1, 128>>>(tokens, base_w, conn_w, gens, out);
    polar_kernel<<<NTOK / 4 / PWARPS, PWARPS * 32>>>(tokens, fiber_w, out);
}